// round 15
// baseline (speedup 1.0000x reference)
#include <cuda_runtime.h>
#include <cstdint>

#define NC 8
#define MM 8192
#define NG 16
#define NB 4
#define NNODES 5461
#define SUBN 341
#define SUBINT 85
#define NBG 64
#define TBLKS 512      // 8 blocks per bg, 2 subtrees per block

__device__ float g_Zpart[NC * 64 * NG];      // per-(c,chunk,g) partial sum of exp(B)
__device__ float g_LB[1024][SUBN * 8];       // [bg*16+q][m*8+i] = logB[lab]-logZ
__device__ float g_leafB[16 * 4096 * 8];     // [g][leaf][i] normalized leaf beta
__device__ float g_rootB[NBG][16 * 8];       // subtree-root beta
__device__ float g_rootW[NBG][16 * 8];       // subtree-root w = e^LB / s
__device__ float g_T[NBG * 256];             // T_acc partials [(k*4+j)*8+i]
__device__ float g_scal[NBG * 2];            // B_lhood, Pi_lhood
__device__ unsigned g_cnt[NBG];              // up-phase completion counters
__device__ unsigned g_cnt2[NBG];             // epilogue counters

__constant__ int cS2[5]  = {5, 21, 85, 341, 1365};   // full start of local level l
__constant__ int cPW[5]  = {1, 4, 16, 64, 256};      // nodes/subtree at local level l
__constant__ int lst[6]  = {0, 1, 5, 21, 85, 341};

// up-node: tb = A_SP-matvec(children betas); LB read from GLOBAL (L1-resident)
#define UPNODE(BTp, RTp, LBp, mm) do {                                       \
    const float eL = __expf(__ldg(&(LBp)[(mm) * 8 + i]));                    \
    float tbp[4];                                                            \
    const float4* cp = (const float4*)&(BTp)[(4 * (mm) + 1) * 8];            \
    _Pragma("unroll")                                                        \
    for (int j = 0; j < 4; j++) {                                            \
        float4 x = cp[2 * j], y = cp[2 * j + 1];                             \
        float t0 = sA_SP[(0 * 4 + j) * 8 + i] * x.x;                         \
        t0 = fmaf(sA_SP[(1 * 4 + j) * 8 + i], x.y, t0);                      \
        t0 = fmaf(sA_SP[(2 * 4 + j) * 8 + i], x.z, t0);                      \
        t0 = fmaf(sA_SP[(3 * 4 + j) * 8 + i], x.w, t0);                      \
        t0 = fmaf(sA_SP[(4 * 4 + j) * 8 + i], y.x, t0);                      \
        t0 = fmaf(sA_SP[(5 * 4 + j) * 8 + i], y.y, t0);                      \
        t0 = fmaf(sA_SP[(6 * 4 + j) * 8 + i], y.z, t0);                      \
        t0 = fmaf(sA_SP[(7 * 4 + j) * 8 + i], y.w, t0);                      \
        tbp[j] = t0;                                                         \
    }                                                                        \
    const float tb = (tbp[0] + tbp[1]) + (tbp[2] + tbp[3]);                  \
    float s = tb * eL;                                                       \
    s += __shfl_xor_sync(gmask, s, 1);                                       \
    s += __shfl_xor_sync(gmask, s, 2);                                       \
    s += __shfl_xor_sync(gmask, s, 4);                                       \
    const float w = __fdividef(eL, s);                                       \
    (RTp)[(mm) * 8 + i] = w;                                                 \
    (BTp)[(mm) * 8 + i] = tb * w;                                            \
} while (0)

// down-node: vectorized AT dot — 8x LDS.128 computes all 4 j-dots at once.
#define DOWNNODE(BTp, RTp, LBp, mm, LEAF) do {                               \
    const int cb_ = 4 * (mm) + 1;                                            \
    const float4 ra = *(const float4*)&(RTp)[(mm) * 8];                      \
    const float4 rb = *(const float4*)&(RTp)[(mm) * 8 + 4];                  \
    float dj[4];                                                             \
    {                                                                        \
        const float4* at4 = ((const float4*)sAT) + i;                        \
        float4 a;                                                            \
        a = at4[0];                                                          \
        dj[0] = ra.x * a.x; dj[1] = ra.x * a.y;                              \
        dj[2] = ra.x * a.z; dj[3] = ra.x * a.w;                              \
        a = at4[8];                                                          \
        dj[0] = fmaf(ra.y, a.x, dj[0]); dj[1] = fmaf(ra.y, a.y, dj[1]);      \
        dj[2] = fmaf(ra.y, a.z, dj[2]); dj[3] = fmaf(ra.y, a.w, dj[3]);      \
        a = at4[16];                                                         \
        dj[0] = fmaf(ra.z, a.x, dj[0]); dj[1] = fmaf(ra.z, a.y, dj[1]);      \
        dj[2] = fmaf(ra.z, a.z, dj[2]); dj[3] = fmaf(ra.z, a.w, dj[3]);      \
        a = at4[24];                                                         \
        dj[0] = fmaf(ra.w, a.x, dj[0]); dj[1] = fmaf(ra.w, a.y, dj[1]);      \
        dj[2] = fmaf(ra.w, a.z, dj[2]); dj[3] = fmaf(ra.w, a.w, dj[3]);      \
        a = at4[32];                                                         \
        dj[0] = fmaf(rb.x, a.x, dj[0]); dj[1] = fmaf(rb.x, a.y, dj[1]);      \
        dj[2] = fmaf(rb.x, a.z, dj[2]); dj[3] = fmaf(rb.x, a.w, dj[3]);      \
        a = at4[40];                                                         \
        dj[0] = fmaf(rb.y, a.x, dj[0]); dj[1] = fmaf(rb.y, a.y, dj[1]);      \
        dj[2] = fmaf(rb.y, a.z, dj[2]); dj[3] = fmaf(rb.y, a.w, dj[3]);      \
        a = at4[48];                                                         \
        dj[0] = fmaf(rb.z, a.x, dj[0]); dj[1] = fmaf(rb.z, a.y, dj[1]);      \
        dj[2] = fmaf(rb.z, a.z, dj[2]); dj[3] = fmaf(rb.z, a.w, dj[3]);      \
        a = at4[56];                                                         \
        dj[0] = fmaf(rb.w, a.x, dj[0]); dj[1] = fmaf(rb.w, a.y, dj[1]);      \
        dj[2] = fmaf(rb.w, a.z, dj[2]); dj[3] = fmaf(rb.w, a.w, dj[3]);      \
    }                                                                        \
    _Pragma("unroll")                                                        \
    for (int j = 0; j < 4; j++) {                                            \
        const float dot = dj[j];                                             \
        const float bci = (BTp)[(cb_ + j) * 8 + i];                          \
        const float ev = bci * dot;                                          \
        accB = fmaf(ev, __ldg(&(LBp)[(cb_ + j) * 8 + i]), accB);             \
        if (LEAF) accPi = fmaf(ev, sLogPi[j * 8 + i], accPi);                \
        else (RTp)[(cb_ + j) * 8 + i] = dot * (RTp)[(cb_ + j) * 8 + i];      \
    }                                                                        \
} while (0)

// ---------------------------------------------------------------------------
// zsum: partial sums of exp(B) per (c,g); zeroes counters. grid = 512.
// ---------------------------------------------------------------------------
__global__ __launch_bounds__(256) void zsum_kernel(const float* __restrict__ Bmat) {
    const int c = blockIdx.x >> 6;
    const int chunk = blockIdx.x & 63;
    const int tid = threadIdx.x;
    const int g4 = tid & 3;
    const int r = tid >> 2;            // 0..63
    __shared__ float red[256 * 4];

    if (blockIdx.x < 64) g_T[blockIdx.x * 256 + tid] = 0.f;
    else if (blockIdx.x == 64 && tid < 128) g_scal[tid] = 0.f;
    else if (blockIdx.x == 65 && tid < 64) g_cnt[tid] = 0u;
    else if (blockIdx.x == 66 && tid < 64) g_cnt2[tid] = 0u;

    const float4* base = (const float4*)(Bmat + ((size_t)c * MM + chunk * 128) * NG) + g4;
    float4 acc = make_float4(0.f, 0.f, 0.f, 0.f);
    #pragma unroll
    for (int e = 0; e < 2; e++) {
        float4 v = __ldg(&base[(size_t)(r + e * 64) * 4]);
        acc.x += __expf(v.x); acc.y += __expf(v.y);
        acc.z += __expf(v.z); acc.w += __expf(v.w);
    }
    ((float4*)red)[g4 * 64 + r] = acc;
    __syncthreads();
    if (tid < 16) {
        const int gg4 = tid >> 2, comp = tid & 3;
        float ss = 0.f;
        #pragma unroll 8
        for (int rr = 0; rr < 64; rr++) ss += red[(gg4 * 64 + rr) * 4 + comp];
        g_Zpart[(c * 64 + chunk) * NG + tid] = ss;
    }
}

#define LOADLZ(dstname)                                                      \
    if (tid < 128) {                                                         \
        const int ii = tid >> 4, gg = tid & 15;                              \
        float z = 0.f;                                                       \
        _Pragma("unroll 8")                                                  \
        for (int h = 0; h < 64; h++) z += g_Zpart[(ii * 64 + h) * NG + gg];  \
        dstname[tid] = __logf(z);                                            \
    }

// ---------------------------------------------------------------------------
// prep: merged lbg (blocks 0..511) + leafb (blocks 512..1023).
// ---------------------------------------------------------------------------
__global__ __launch_bounds__(256) void prep_kernel(
    const int* __restrict__ labels, const float* __restrict__ Bmat,
    const float* __restrict__ Pi)
{
    const int tid = threadIdx.x;
    __shared__ float sLZ[128];   // [i*16+g]
    __shared__ float sPiL[512];  // [g*32 + pos*8 + i] (leafb only)

    LOADLZ(sLZ)

    if (blockIdx.x < 512) {
        const int e = blockIdx.x & 7;
        const int q = (blockIdx.x >> 3) & 15;
        const int b = blockIdx.x >> 7;
        const int slot = tid >> 5;
        const int lane = tid & 31;
        const int i = lane & 7;
        const int g4 = lane >> 3;
        __syncthreads();

        const int* lab = labels + b * NNODES;
        const int m0 = e * 43;
        const int mend = (m0 + 43 < SUBN) ? m0 + 43 : SUBN;
        for (int m = m0 + slot; m < mend; m += 8) {
            const int l = (m >= 85) ? 4 : (m >= 21) ? 3 : (m >= 5) ? 2 : (m >= 1) ? 1 : 0;
            const int n = cS2[l] + q * cPW[l] + (m - lst[l]);
            const int lbl = __ldg(&lab[n]);
            const float4 v = __ldg((const float4*)(Bmat + ((size_t)i * MM + lbl) * NG) + g4);
            float vals[4] = {v.x, v.y, v.z, v.w};
            #pragma unroll
            for (int k = 0; k < 4; k++) {
                const int g = g4 * 4 + k;
                g_LB[(b * 16 + g) * 16 + q][m * 8 + i] = vals[k] - sLZ[i * 16 + g];
            }
        }
    } else {
        const int blkL = blockIdx.x - 512;
        const int i = tid & 7;
        const int g = (tid >> 3) & 15;
        const int slot = tid >> 7;
        const unsigned gmask = 0xFFu << (tid & 24);

        for (int idx = tid; idx < 512; idx += 256) {
            const int gg = idx >> 5, pos = (idx >> 3) & 3, c = idx & 7;
            float t[8]; float mxv = -1e30f;
            #pragma unroll
            for (int cc = 0; cc < 8; cc++) {
                t[cc] = __ldg(&Pi[(cc * 4 + pos) * NG + gg]);
                mxv = fmaxf(mxv, t[cc]);
            }
            float s = 0.f;
            #pragma unroll
            for (int cc = 0; cc < 8; cc++) s += __expf(t[cc] - mxv);
            float ls = __logf(s);
            float val = 0.f;
            #pragma unroll
            for (int cc = 0; cc < 8; cc++) if (cc == c) val = __expf(t[cc] - mxv - ls);
            sPiL[idx] = val;
        }
        __syncthreads();

        const float lz = sLZ[i * 16 + g];
        #pragma unroll
        for (int it = 0; it < 4; it++) {
            const int leaf = blkL * 8 + it * 2 + slot;
            const int n = 1365 + leaf;
            const int pos = leaf & 3;
            float v = sPiL[g * 32 + pos * 8 + i]
                    * __expf(__ldg(Bmat + ((size_t)i * MM + n) * NG + g) - lz);
            float s = v;
            s += __shfl_xor_sync(gmask, s, 1);
            s += __shfl_xor_sync(gmask, s, 2);
            s += __shfl_xor_sync(gmask, s, 4);
            g_leafB[((size_t)g * 4096 + leaf) * 8 + i] = __fdividef(v, s);
        }
    }
}

// ---------------------------------------------------------------------------
// Fused tree kernel: grid = 512, block = 256 (32 groups of 8 lanes).
// ---------------------------------------------------------------------------
__global__ __launch_bounds__(256, 4) void tree_kernel(
    const int* __restrict__ labels, const float* __restrict__ A,
    const float* __restrict__ Bmat, const float* __restrict__ Pi,
    const float* __restrict__ SP, float* __restrict__ out)
{
    extern __shared__ float dyn[];
    float* sBeta = dyn;                        // [2][SUBN*8]
    float* sRT   = dyn + 2 * SUBN * 8;         // [2][SUBINT*8]  w -> ratio
    float* sTp   = dyn + 2 * SUBN * 8 + 2 * SUBINT * 8;  // [4][256]

    const int blk = blockIdx.x;
    const int q8 = blk & 7;
    const int bg = blk >> 3;
    const int g = bg & 15;
    const int b = bg >> 4;
    const int tid = threadIdx.x;
    const int i = tid & 7;
    const int grp = tid >> 3;                  // 32 groups
    const unsigned gmask = 0xFFu << (tid & 24);
    const bool top = (q8 == 0);

    __shared__ float sA_SP[256];
    __shared__ float sAT[256];
    __shared__ float sLogPi[32];
    __shared__ float sLogZ[128];
    __shared__ float sSP[4], sLogSP[4];
    __shared__ float sRootB[128], sRootW[128];
    __shared__ float sB1[32], sW1[32], sR1[32], sRr[8];
    __shared__ float sT[256];
    __shared__ float sBl, sPil, sAred[4];
    __shared__ unsigned sRank;

    // ---- setup ----
    if (tid == 0) {
        float t[4]; float mxv = -1e30f;
        #pragma unroll
        for (int j = 0; j < 4; j++) { t[j] = SP[j * NG + g]; mxv = fmaxf(mxv, t[j]); }
        float s = 0.f;
        #pragma unroll
        for (int j = 0; j < 4; j++) s += __expf(t[j] - mxv);
        float ls = __logf(s);
        #pragma unroll
        for (int j = 0; j < 4; j++) {
            sSP[j] = __expf(t[j] - mxv - ls);
            sLogSP[j] = t[j] - mxv - ls;
            sAred[j] = 0.f;
        }
        sBl = 0.f; sPil = 0.f;
    }
    LOADLZ(sLogZ)
    if (tid >= 160 && tid < 164) {
        const int pos = tid - 160;
        float t[8]; float mxv = -1e30f;
        #pragma unroll
        for (int c = 0; c < 8; c++) { t[c] = Pi[(c * 4 + pos) * NG + g]; mxv = fmaxf(mxv, t[c]); }
        float s = 0.f;
        #pragma unroll
        for (int c = 0; c < 8; c++) s += __expf(t[c] - mxv);
        float ls = __logf(s);
        #pragma unroll
        for (int c = 0; c < 8; c++) sLogPi[pos * 8 + c] = t[c] - mxv - ls;
    }
    sT[tid] = 0.f;
    __syncthreads();
    if (tid < 32) {
        const int kj = tid;
        const int k = kj >> 2;
        const int j = kj & 3;
        float t[8]; float mxv = -1e30f;
        #pragma unroll
        for (int c = 0; c < 8; c++) { t[c] = A[(size_t)(c * 32 + kj) * NG + g]; mxv = fmaxf(mxv, t[c]); }
        float s = 0.f;
        #pragma unroll
        for (int c = 0; c < 8; c++) s += __expf(t[c] - mxv);
        float ls = __logf(s);
        const float spj = sSP[j];
        #pragma unroll
        for (int c = 0; c < 8; c++) {
            float asp = __expf(t[c] - mxv - ls) * spj;
            sA_SP[kj * 8 + c] = asp;
            sAT[c * 32 + k * 4 + j] = asp;
        }
    }

    const int* lab = labels + b * NNODES;
    const float* Brow = Bmat + (size_t)i * (MM * NG) + g;
    const float* LB0 = g_LB[bg * 16 + 2 * q8];
    const float* LB1 = g_LB[bg * 16 + 2 * q8 + 1];

    // ---- stage leaf betas only ----
    #pragma unroll
    for (int sidx = 0; sidx < 2; sidx++) {
        const int q = 2 * q8 + sidx;
        float4* dl = (float4*)(sBeta + sidx * SUBN * 8 + 85 * 8);
        const float4* sl = (const float4*)(g_leafB + ((size_t)g * 4096 + q * 256) * 8);
        for (int idx = tid; idx < 512; idx += 256) dl[idx] = sl[idx];
    }
    __syncthreads();
    const float lz = sLogZ[i * 16 + g];

    // ======== UP: one chunk per group ========
    {
        const int sidx = grp >> 4;
        const int c = grp & 15;
        float* BT = sBeta + sidx * SUBN * 8;
        float* RT = sRT + sidx * SUBINT * 8;
        const float* LB = sidx ? LB1 : LB0;
        #pragma unroll
        for (int t = 0; t < 4; t++)
            UPNODE(BT, RT, LB, 21 + 4 * c + t);
        __syncwarp();
        UPNODE(BT, RT, LB, 5 + c);
    }
    __syncthreads();

    if (grp < 8) {
        const int sidx = grp >> 2;
        const int jn = grp & 3;
        float* BT = sBeta + sidx * SUBN * 8;
        float* RT = sRT + sidx * SUBINT * 8;
        const float* LB = sidx ? LB1 : LB0;
        UPNODE(BT, RT, LB, 1 + jn);
    }
    __syncthreads();

    if (grp < 2) {
        const int sidx = grp;
        float* BT = sBeta + sidx * SUBN * 8;
        float* RT = sRT + sidx * SUBINT * 8;
        const float* LB = sidx ? LB1 : LB0;
        UPNODE(BT, RT, LB, 0);
    }
    __syncthreads();

    // ---- publish subtree roots, spin-sync within bg ----
    if (tid < 16) {
        const int sidx = tid >> 3;
        const int q = 2 * q8 + sidx;
        g_rootB[bg][q * 8 + i] = sBeta[sidx * SUBN * 8 + i];
        g_rootW[bg][q * 8 + i] = sRT[sidx * SUBINT * 8 + i];
    }
    __threadfence();
    __syncthreads();
    if (tid == 0) {
        atomicAdd(&g_cnt[bg], 1u);
        while (((volatile unsigned*)g_cnt)[bg] < 8u) __nanosleep(64);
    }
    __syncthreads();
    __threadfence();

    if (tid < 128) {
        const int p = tid >> 3;
        sRootB[tid] = ((volatile float*)g_rootB[bg])[p * 8 + i];
        sRootW[tid] = ((volatile float*)g_rootW[bg])[p * 8 + i];
    }
    __syncthreads();

    float accB = 0.f, accPi = 0.f;

    // ======== top-tree (nodes 0..20), recomputed redundantly ========
    if (tid < 32) {
        const int g4 = grp;
        float tb = 0.f;
        const float4* cp = (const float4*)&sRootB[(4 * g4) * 8];
        #pragma unroll
        for (int j = 0; j < 4; j++) {
            float4 x = cp[2 * j], y = cp[2 * j + 1];
            tb = fmaf(sA_SP[(0 * 4 + j) * 8 + i], x.x, tb);
            tb = fmaf(sA_SP[(1 * 4 + j) * 8 + i], x.y, tb);
            tb = fmaf(sA_SP[(2 * 4 + j) * 8 + i], x.z, tb);
            tb = fmaf(sA_SP[(3 * 4 + j) * 8 + i], x.w, tb);
            tb = fmaf(sA_SP[(4 * 4 + j) * 8 + i], y.x, tb);
            tb = fmaf(sA_SP[(5 * 4 + j) * 8 + i], y.y, tb);
            tb = fmaf(sA_SP[(6 * 4 + j) * 8 + i], y.z, tb);
            tb = fmaf(sA_SP[(7 * 4 + j) * 8 + i], y.w, tb);
        }
        const int lbl = __ldg(&lab[1 + g4]);
        const float eL = __expf(__ldg(&Brow[(size_t)lbl * NG]) - lz);
        float s = tb * eL;
        s += __shfl_xor_sync(gmask, s, 1);
        s += __shfl_xor_sync(gmask, s, 2);
        s += __shfl_xor_sync(gmask, s, 4);
        const float w = __fdividef(eL, s);
        sW1[g4 * 8 + i] = w;
        sB1[g4 * 8 + i] = tb * w;
    }
    __syncthreads();

    if (tid < 8) {
        float tb = 0.f;
        #pragma unroll
        for (int j = 0; j < 4; j++)
            #pragma unroll
            for (int k = 0; k < 8; k++)
                tb = fmaf(sA_SP[(k * 4 + j) * 8 + i], sB1[j * 8 + k], tb);
        const int lbl = __ldg(&lab[0]);
        const float lB = __ldg(&Brow[(size_t)lbl * NG]) - lz;
        const float eL = __expf(lB);
        float s = tb * eL;
        s += __shfl_xor_sync(gmask, s, 1);
        s += __shfl_xor_sync(gmask, s, 2);
        s += __shfl_xor_sync(gmask, s, 4);
        const float w = __fdividef(eL, s);
        sRr[i] = w;
        if (top) accB = fmaf(tb * w, lB, accB);
    }
    __syncthreads();

    if (tid < 32) {
        const int j = grp;
        float dot = 0.f;
        #pragma unroll
        for (int ii = 0; ii < 8; ii++)
            dot = fmaf(sRr[ii], sAT[ii * 32 + i * 4 + j], dot);
        const float ev = sB1[j * 8 + i] * dot;
        sR1[j * 8 + i] = dot * sW1[j * 8 + i];
        if (top) {
            const int lbl = __ldg(&lab[1 + j]);
            accB = fmaf(ev, __ldg(&Brow[(size_t)lbl * NG]) - lz, accB);
            const float rr = sRr[i];
            #pragma unroll
            for (int k = 0; k < 8; k++)
                atomicAdd(&sT[(k * 4 + j) * 8 + i],
                          rr * sA_SP[(k * 4 + j) * 8 + i] * sB1[j * 8 + k]);
        }
    }
    __syncthreads();

    if (tid < 128) {
        const int p = tid >> 3;
        const int nidx = p >> 2;
        const int j = p & 3;
        float dot = 0.f;
        #pragma unroll
        for (int ii = 0; ii < 8; ii++)
            dot = fmaf(sR1[nidx * 8 + ii], sAT[ii * 32 + i * 4 + j], dot);
        const float ev = sRootB[p * 8 + i] * dot;
        const float r2 = dot * sRootW[p * 8 + i];
        if (p == 2 * q8)     sRT[i] = r2;
        if (p == 2 * q8 + 1) sRT[SUBINT * 8 + i] = r2;
        if (top) {
            const int lbl = __ldg(&lab[5 + p]);
            accB = fmaf(ev, __ldg(&Brow[(size_t)lbl * NG]) - lz, accB);
            const float r1v = sR1[nidx * 8 + i];
            #pragma unroll
            for (int k = 0; k < 8; k++)
                atomicAdd(&sT[(k * 4 + j) * 8 + i],
                          r1v * sA_SP[(k * 4 + j) * 8 + i] * sRootB[p * 8 + k]);
        }
    }
    __syncthreads();

    // ======== DOWN ========
    if (grp < 2) {
        const int sidx = grp;
        float* BT = sBeta + sidx * SUBN * 8;
        float* RT = sRT + sidx * SUBINT * 8;
        const float* LB = sidx ? LB1 : LB0;
        DOWNNODE(BT, RT, LB, 0, false);
    }
    __syncthreads();

    if (grp < 8) {
        const int sidx = grp >> 2;
        const int jn = grp & 3;
        float* BT = sBeta + sidx * SUBN * 8;
        float* RT = sRT + sidx * SUBINT * 8;
        const float* LB = sidx ? LB1 : LB0;
        DOWNNODE(BT, RT, LB, 1 + jn, false);
    }
    __syncthreads();

    {
        const int sidx = grp >> 4;
        const int c = grp & 15;
        float* BT = sBeta + sidx * SUBN * 8;
        float* RT = sRT + sidx * SUBINT * 8;
        const float* LB = sidx ? LB1 : LB0;
        DOWNNODE(BT, RT, LB, 5 + c, false);
        __syncwarp();
        #pragma unroll
        for (int t = 0; t < 4; t++)
            DOWNNODE(BT, RT, LB, 21 + 4 * c + t, true);
    }
    __syncthreads();

    // ======== vectorized T post-pass (private slice banks) ========
    {
        const int slice = tid >> 6;
        const int jp = (tid >> 4) & 3;
        const int kh = (tid >> 3) & 1;
        const int ip = tid & 7;
        float a0 = 0.f, a1 = 0.f, a2 = 0.f, a3 = 0.f;
        #pragma unroll
        for (int sidx = 0; sidx < 2; sidx++) {
            const float* RTp = sRT + sidx * SUBINT * 8 + slice * 8 + ip;
            const float* BTp = sBeta + sidx * SUBN * 8 + (4 * slice + 1 + jp) * 8 + kh * 4;
            #pragma unroll 4
            for (int m = slice; m < SUBINT; m += 4) {
                const float r = *RTp;
                const float4 bv = *(const float4*)BTp;
                a0 = fmaf(r, bv.x, a0);
                a1 = fmaf(r, bv.y, a1);
                a2 = fmaf(r, bv.z, a2);
                a3 = fmaf(r, bv.w, a3);
                RTp += 32;
                BTp += 128;
            }
        }
        const int k0 = kh * 4;
        float* bank = sTp + slice * 256;
        bank[((k0 + 0) * 4 + jp) * 8 + ip] = a0 * sA_SP[((k0 + 0) * 4 + jp) * 8 + ip];
        bank[((k0 + 1) * 4 + jp) * 8 + ip] = a1 * sA_SP[((k0 + 1) * 4 + jp) * 8 + ip];
        bank[((k0 + 2) * 4 + jp) * 8 + ip] = a2 * sA_SP[((k0 + 2) * 4 + jp) * 8 + ip];
        bank[((k0 + 3) * 4 + jp) * 8 + ip] = a3 * sA_SP[((k0 + 3) * 4 + jp) * 8 + ip];
    }
    __syncthreads();
    {
        const float tsum = (sTp[tid] + sTp[256 + tid]) + (sTp[512 + tid] + sTp[768 + tid]);
        sT[tid] += tsum;
    }

    // ---- scalar reductions ----
    #pragma unroll
    for (int off = 1; off < 32; off <<= 1) {
        accB += __shfl_xor_sync(0xFFFFFFFFu, accB, off);
        accPi += __shfl_xor_sync(0xFFFFFFFFu, accPi, off);
    }
    if ((tid & 31) == 0) {
        atomicAdd(&sBl, accB);
        atomicAdd(&sPil, accPi);
    }
    __syncthreads();

    atomicAdd(&g_T[bg * 256 + tid], sT[tid]);
    if (tid == 0) {
        atomicAdd(&g_scal[bg * 2 + 0], sBl);
        atomicAdd(&g_scal[bg * 2 + 1], sPil);
    }

    // ======== fused epilogue ========
    __threadfence();
    __syncthreads();
    if (tid == 0) sRank = atomicAdd(&g_cnt2[bg], 1u);
    __syncthreads();
    if (sRank == 7u) {
        __threadfence();
        const float T = g_T[bg * 256 + tid];
        const int kj = tid >> 3;
        const int ii = tid & 7;
        const int j = kj & 3;
        const int k = kj >> 2;
        float t[8]; float mxv = -1e30f;
        #pragma unroll
        for (int c = 0; c < 8; c++) {
            t[c] = __ldg(&A[(size_t)(c * 32 + kj) * NG + g]);
            mxv = fmaxf(mxv, t[c]);
        }
        float s = 0.f;
        #pragma unroll
        for (int c = 0; c < 8; c++) s += __expf(t[c] - mxv);
        float logA = 0.f;
        #pragma unroll
        for (int c = 0; c < 8; c++)
            if (c == ii) logA = t[c] - mxv - __logf(s);
        atomicAdd(&sAred[j], T * logA);
        __syncthreads();
        const float ll = sAred[j] + g_scal[bg * 2 + 0] + g_scal[bg * 2 + 1]
                       + T * sLogSP[j];
        out[((((size_t)b * 8 + ii) * 8 + k) * 4 + j) * NG + g] = -ll;
    }
}

#define TREE_DYN_BYTES ((2 * SUBN * 8 + 2 * SUBINT * 8 + 4 * 256) * 4)  // 31360 B

extern "C" void kernel_launch(void* const* d_in, const int* in_sizes, int n_in,
                              void* d_out, int out_size) {
    const int*   labels = (const int*)d_in[0];
    const float* A      = (const float*)d_in[1];
    const float* Bmat   = (const float*)d_in[2];
    const float* Pi     = (const float*)d_in[3];
    const float* SP     = (const float*)d_in[4];
    float* out = (float*)d_out;

    cudaFuncSetAttribute(tree_kernel,
                         cudaFuncAttributeMaxDynamicSharedMemorySize, TREE_DYN_BYTES);

    zsum_kernel<<<512, 256>>>(Bmat);
    prep_kernel<<<1024, 256>>>(labels, Bmat, Pi);
    tree_kernel<<<TBLKS, 256, TREE_DYN_BYTES>>>(labels, A, Bmat, Pi, SP, out);
}

// round 16
// speedup vs baseline: 1.0455x; 1.0455x over previous
#include <cuda_runtime.h>
#include <cstdint>

#define NC 8
#define MM 8192
#define NG 16
#define NB 4
#define NNODES 5461
#define SUBN 341
#define SUBINT 85
#define NBG 64
#define TBLKS 512      // 8 blocks per bg, 2 subtrees per block

__device__ float g_Zpart[NC * 32 * NG];      // per-(c,chunk,g) partial sum of exp(B)
__device__ float g_LB[1024][SUBN * 8];       // [bg*16+q][m*8+i] = logB[lab]-logZ
__device__ float g_leafB[16 * 4096 * 8];     // [g][leaf][i] normalized leaf beta
__device__ float g_rootB[NBG][16 * 8];       // subtree-root beta
__device__ float g_rootW[NBG][16 * 8];       // subtree-root w = e^LB / s
__device__ float g_T[NBG * 256];             // T_acc partials [(k*4+j)*8+i]
__device__ float g_scal[NBG * 2];            // B_lhood, Pi_lhood
__device__ unsigned g_cnt[NBG];              // up-phase completion counters
__device__ unsigned g_cnt2[NBG];             // epilogue counters

__constant__ int cS2[5]  = {5, 21, 85, 341, 1365};   // full start of local level l
__constant__ int cPW[5]  = {1, 4, 16, 64, 256};      // nodes/subtree at local level l
__constant__ int lst[6]  = {0, 1, 5, 21, 85, 341};

// up-node: tb = A_SP-matvec(children betas); LB read from GLOBAL (L1-resident)
#define UPNODE(BTp, RTp, LBp, mm) do {                                       \
    const float eL = __expf(__ldg(&(LBp)[(mm) * 8 + i]));                    \
    float tbp[4];                                                            \
    const float4* cp = (const float4*)&(BTp)[(4 * (mm) + 1) * 8];            \
    _Pragma("unroll")                                                        \
    for (int j = 0; j < 4; j++) {                                            \
        float4 x = cp[2 * j], y = cp[2 * j + 1];                             \
        float t0 = sA_SP[(0 * 4 + j) * 8 + i] * x.x;                         \
        t0 = fmaf(sA_SP[(1 * 4 + j) * 8 + i], x.y, t0);                      \
        t0 = fmaf(sA_SP[(2 * 4 + j) * 8 + i], x.z, t0);                      \
        t0 = fmaf(sA_SP[(3 * 4 + j) * 8 + i], x.w, t0);                      \
        t0 = fmaf(sA_SP[(4 * 4 + j) * 8 + i], y.x, t0);                      \
        t0 = fmaf(sA_SP[(5 * 4 + j) * 8 + i], y.y, t0);                      \
        t0 = fmaf(sA_SP[(6 * 4 + j) * 8 + i], y.z, t0);                      \
        t0 = fmaf(sA_SP[(7 * 4 + j) * 8 + i], y.w, t0);                      \
        tbp[j] = t0;                                                         \
    }                                                                        \
    const float tb = (tbp[0] + tbp[1]) + (tbp[2] + tbp[3]);                  \
    float s = tb * eL;                                                       \
    s += __shfl_xor_sync(gmask, s, 1);                                       \
    s += __shfl_xor_sync(gmask, s, 2);                                       \
    s += __shfl_xor_sync(gmask, s, 4);                                       \
    const float w = __fdividef(eL, s);                                       \
    (RTp)[(mm) * 8 + i] = w;                                                 \
    (BTp)[(mm) * 8 + i] = tb * w;                                            \
} while (0)

// down-node: AT via float2 loads (16 LDS.64/node), j handled in pairs to
// keep live-register count inside the 64-reg budget.
#define DOWNNODE(BTp, RTp, LBp, mm, LEAF) do {                               \
    const int cb_ = 4 * (mm) + 1;                                            \
    const float4 ra = *(const float4*)&(RTp)[(mm) * 8];                      \
    const float4 rb = *(const float4*)&(RTp)[(mm) * 8 + 4];                  \
    _Pragma("unroll")                                                        \
    for (int jp = 0; jp < 2; jp++) {                                         \
        const float2* at2 = (const float2*)(sAT + i * 4 + jp * 2);           \
        float2 a;                                                            \
        float e0, e1;                                                        \
        a = at2[0];  e0 = ra.x * a.x; e1 = ra.x * a.y;                       \
        a = at2[16]; e0 = fmaf(ra.y, a.x, e0); e1 = fmaf(ra.y, a.y, e1);     \
        a = at2[32]; e0 = fmaf(ra.z, a.x, e0); e1 = fmaf(ra.z, a.y, e1);     \
        a = at2[48]; e0 = fmaf(ra.w, a.x, e0); e1 = fmaf(ra.w, a.y, e1);     \
        a = at2[64]; e0 = fmaf(rb.x, a.x, e0); e1 = fmaf(rb.x, a.y, e1);     \
        a = at2[80]; e0 = fmaf(rb.y, a.x, e0); e1 = fmaf(rb.y, a.y, e1);     \
        a = at2[96]; e0 = fmaf(rb.z, a.x, e0); e1 = fmaf(rb.z, a.y, e1);     \
        a = at2[112]; e0 = fmaf(rb.w, a.x, e0); e1 = fmaf(rb.w, a.y, e1);    \
        const int j0 = 2 * jp, j1 = 2 * jp + 1;                              \
        {                                                                    \
            const float bci = (BTp)[(cb_ + j0) * 8 + i];                     \
            const float ev = bci * e0;                                       \
            accB = fmaf(ev, __ldg(&(LBp)[(cb_ + j0) * 8 + i]), accB);        \
            if (LEAF) accPi = fmaf(ev, sLogPi[j0 * 8 + i], accPi);           \
            else (RTp)[(cb_ + j0) * 8 + i] = e0 * (RTp)[(cb_ + j0) * 8 + i]; \
        }                                                                    \
        {                                                                    \
            const float bci = (BTp)[(cb_ + j1) * 8 + i];                     \
            const float ev = bci * e1;                                       \
            accB = fmaf(ev, __ldg(&(LBp)[(cb_ + j1) * 8 + i]), accB);        \
            if (LEAF) accPi = fmaf(ev, sLogPi[j1 * 8 + i], accPi);           \
            else (RTp)[(cb_ + j1) * 8 + i] = e1 * (RTp)[(cb_ + j1) * 8 + i]; \
        }                                                                    \
    }                                                                        \
} while (0)

// ---------------------------------------------------------------------------
// zsum: partial sums of exp(B) per (c,g); zeroes counters. grid = 256.
// ---------------------------------------------------------------------------
__global__ __launch_bounds__(256) void zsum_kernel(const float* __restrict__ Bmat) {
    const int c = blockIdx.x >> 5;
    const int chunk = blockIdx.x & 31;
    const int tid = threadIdx.x;
    const int g4 = tid & 3;
    const int r = tid >> 2;
    __shared__ float red[256 * 4];

    const int zid = blockIdx.x * 256 + tid;
    if (zid < NBG * 256) g_T[zid] = 0.f;
    else if (zid < NBG * 256 + 128) g_scal[zid - NBG * 256] = 0.f;
    else if (zid < NBG * 256 + 192) g_cnt[zid - NBG * 256 - 128] = 0u;
    else if (zid < NBG * 256 + 256) g_cnt2[zid - NBG * 256 - 192] = 0u;

    const float4* base = (const float4*)(Bmat + ((size_t)c * MM + chunk * 256) * NG) + g4;
    float4 acc = make_float4(0.f, 0.f, 0.f, 0.f);
    #pragma unroll
    for (int e = 0; e < 4; e++) {
        float4 v = __ldg(&base[(size_t)(r + e * 64) * 4]);
        acc.x += __expf(v.x); acc.y += __expf(v.y);
        acc.z += __expf(v.z); acc.w += __expf(v.w);
    }
    ((float4*)red)[g4 * 64 + r] = acc;
    __syncthreads();
    if (tid < 16) {
        const int gg4 = tid >> 2, comp = tid & 3;
        float ss = 0.f;
        #pragma unroll 8
        for (int rr = 0; rr < 64; rr++) ss += red[(gg4 * 64 + rr) * 4 + comp];
        g_Zpart[(c * 32 + chunk) * NG + tid] = ss;
    }
}

#define LOADLZ(dstname)                                                      \
    if (tid < 128) {                                                         \
        const int ii = tid >> 4, gg = tid & 15;                              \
        float z = 0.f;                                                       \
        _Pragma("unroll 8")                                                  \
        for (int h = 0; h < 32; h++) z += g_Zpart[(ii * 32 + h) * NG + gg];  \
        dstname[tid] = __logf(z);                                            \
    }

// ---------------------------------------------------------------------------
// prep: merged lbg (blocks 0..511) + leafb (blocks 512..1023).
// ---------------------------------------------------------------------------
__global__ __launch_bounds__(256) void prep_kernel(
    const int* __restrict__ labels, const float* __restrict__ Bmat,
    const float* __restrict__ Pi)
{
    const int tid = threadIdx.x;
    __shared__ float sLZ[128];   // [i*16+g]
    __shared__ float sPiL[512];  // [g*32 + pos*8 + i] (leafb only)

    LOADLZ(sLZ)

    if (blockIdx.x < 512) {
        const int e = blockIdx.x & 7;
        const int q = (blockIdx.x >> 3) & 15;
        const int b = blockIdx.x >> 7;
        const int slot = tid >> 5;
        const int lane = tid & 31;
        const int i = lane & 7;
        const int g4 = lane >> 3;
        __syncthreads();

        const int* lab = labels + b * NNODES;
        const int m0 = e * 43;
        const int mend = (m0 + 43 < SUBN) ? m0 + 43 : SUBN;
        for (int m = m0 + slot; m < mend; m += 8) {
            const int l = (m >= 85) ? 4 : (m >= 21) ? 3 : (m >= 5) ? 2 : (m >= 1) ? 1 : 0;
            const int n = cS2[l] + q * cPW[l] + (m - lst[l]);
            const int lbl = __ldg(&lab[n]);
            const float4 v = __ldg((const float4*)(Bmat + ((size_t)i * MM + lbl) * NG) + g4);
            float vals[4] = {v.x, v.y, v.z, v.w};
            #pragma unroll
            for (int k = 0; k < 4; k++) {
                const int g = g4 * 4 + k;
                g_LB[(b * 16 + g) * 16 + q][m * 8 + i] = vals[k] - sLZ[i * 16 + g];
            }
        }
    } else {
        const int blkL = blockIdx.x - 512;
        const int i = tid & 7;
        const int g = (tid >> 3) & 15;
        const int slot = tid >> 7;
        const unsigned gmask = 0xFFu << (tid & 24);

        for (int idx = tid; idx < 512; idx += 256) {
            const int gg = idx >> 5, pos = (idx >> 3) & 3, c = idx & 7;
            float t[8]; float mxv = -1e30f;
            #pragma unroll
            for (int cc = 0; cc < 8; cc++) {
                t[cc] = __ldg(&Pi[(cc * 4 + pos) * NG + gg]);
                mxv = fmaxf(mxv, t[cc]);
            }
            float s = 0.f;
            #pragma unroll
            for (int cc = 0; cc < 8; cc++) s += __expf(t[cc] - mxv);
            float ls = __logf(s);
            float val = 0.f;
            #pragma unroll
            for (int cc = 0; cc < 8; cc++) if (cc == c) val = __expf(t[cc] - mxv - ls);
            sPiL[idx] = val;
        }
        __syncthreads();

        const float lz = sLZ[i * 16 + g];
        #pragma unroll
        for (int it = 0; it < 4; it++) {
            const int leaf = blkL * 8 + it * 2 + slot;
            const int n = 1365 + leaf;
            const int pos = leaf & 3;
            float v = sPiL[g * 32 + pos * 8 + i]
                    * __expf(__ldg(Bmat + ((size_t)i * MM + n) * NG + g) - lz);
            float s = v;
            s += __shfl_xor_sync(gmask, s, 1);
            s += __shfl_xor_sync(gmask, s, 2);
            s += __shfl_xor_sync(gmask, s, 4);
            g_leafB[((size_t)g * 4096 + leaf) * 8 + i] = __fdividef(v, s);
        }
    }
}

// ---------------------------------------------------------------------------
// Fused tree kernel: grid = 512, block = 256 (32 groups of 8 lanes).
// ---------------------------------------------------------------------------
__global__ __launch_bounds__(256, 4) void tree_kernel(
    const int* __restrict__ labels, const float* __restrict__ A,
    const float* __restrict__ Bmat, const float* __restrict__ Pi,
    const float* __restrict__ SP, float* __restrict__ out)
{
    extern __shared__ float dyn[];
    float* sBeta = dyn;                        // [2][SUBN*8]
    float* sRT   = dyn + 2 * SUBN * 8;         // [2][SUBINT*8]  w -> ratio
    float* sTp   = dyn + 2 * SUBN * 8 + 2 * SUBINT * 8;  // [4][256]

    const int blk = blockIdx.x;
    const int q8 = blk & 7;
    const int bg = blk >> 3;
    const int g = bg & 15;
    const int b = bg >> 4;
    const int tid = threadIdx.x;
    const int i = tid & 7;
    const int grp = tid >> 3;                  // 32 groups
    const unsigned gmask = 0xFFu << (tid & 24);
    const bool top = (q8 == 0);

    __shared__ float sA_SP[256];
    __shared__ float sAT[256];
    __shared__ float sLogPi[32];
    __shared__ float sLogZ[128];
    __shared__ float sSP[4], sLogSP[4];
    __shared__ float sRootB[128], sRootW[128];
    __shared__ float sB1[32], sW1[32], sR1[32], sRr[8];
    __shared__ float sT[256];
    __shared__ float sBl, sPil, sAred[4];
    __shared__ unsigned sRank;

    // ---- setup ----
    if (tid == 0) {
        float t[4]; float mxv = -1e30f;
        #pragma unroll
        for (int j = 0; j < 4; j++) { t[j] = SP[j * NG + g]; mxv = fmaxf(mxv, t[j]); }
        float s = 0.f;
        #pragma unroll
        for (int j = 0; j < 4; j++) s += __expf(t[j] - mxv);
        float ls = __logf(s);
        #pragma unroll
        for (int j = 0; j < 4; j++) {
            sSP[j] = __expf(t[j] - mxv - ls);
            sLogSP[j] = t[j] - mxv - ls;
            sAred[j] = 0.f;
        }
        sBl = 0.f; sPil = 0.f;
    }
    LOADLZ(sLogZ)
    if (tid >= 160 && tid < 164) {
        const int pos = tid - 160;
        float t[8]; float mxv = -1e30f;
        #pragma unroll
        for (int c = 0; c < 8; c++) { t[c] = Pi[(c * 4 + pos) * NG + g]; mxv = fmaxf(mxv, t[c]); }
        float s = 0.f;
        #pragma unroll
        for (int c = 0; c < 8; c++) s += __expf(t[c] - mxv);
        float ls = __logf(s);
        #pragma unroll
        for (int c = 0; c < 8; c++) sLogPi[pos * 8 + c] = t[c] - mxv - ls;
    }
    sT[tid] = 0.f;
    __syncthreads();
    if (tid < 32) {
        const int kj = tid;
        const int k = kj >> 2;
        const int j = kj & 3;
        float t[8]; float mxv = -1e30f;
        #pragma unroll
        for (int c = 0; c < 8; c++) { t[c] = A[(size_t)(c * 32 + kj) * NG + g]; mxv = fmaxf(mxv, t[c]); }
        float s = 0.f;
        #pragma unroll
        for (int c = 0; c < 8; c++) s += __expf(t[c] - mxv);
        float ls = __logf(s);
        const float spj = sSP[j];
        #pragma unroll
        for (int c = 0; c < 8; c++) {
            float asp = __expf(t[c] - mxv - ls) * spj;
            sA_SP[kj * 8 + c] = asp;
            sAT[c * 32 + k * 4 + j] = asp;
        }
    }

    const int* lab = labels + b * NNODES;
    const float* Brow = Bmat + (size_t)i * (MM * NG) + g;
    const float* LB0 = g_LB[bg * 16 + 2 * q8];
    const float* LB1 = g_LB[bg * 16 + 2 * q8 + 1];

    // ---- stage leaf betas only ----
    #pragma unroll
    for (int sidx = 0; sidx < 2; sidx++) {
        const int q = 2 * q8 + sidx;
        float4* dl = (float4*)(sBeta + sidx * SUBN * 8 + 85 * 8);
        const float4* sl = (const float4*)(g_leafB + ((size_t)g * 4096 + q * 256) * 8);
        for (int idx = tid; idx < 512; idx += 256) dl[idx] = sl[idx];
    }
    __syncthreads();
    const float lz = sLogZ[i * 16 + g];

    // ======== UP: one chunk per group ========
    {
        const int sidx = grp >> 4;
        const int c = grp & 15;
        float* BT = sBeta + sidx * SUBN * 8;
        float* RT = sRT + sidx * SUBINT * 8;
        const float* LB = sidx ? LB1 : LB0;
        #pragma unroll
        for (int t = 0; t < 4; t++)
            UPNODE(BT, RT, LB, 21 + 4 * c + t);
        __syncwarp();
        UPNODE(BT, RT, LB, 5 + c);
    }
    __syncthreads();

    if (grp < 8) {
        const int sidx = grp >> 2;
        const int jn = grp & 3;
        float* BT = sBeta + sidx * SUBN * 8;
        float* RT = sRT + sidx * SUBINT * 8;
        const float* LB = sidx ? LB1 : LB0;
        UPNODE(BT, RT, LB, 1 + jn);
    }
    __syncthreads();

    if (grp < 2) {
        const int sidx = grp;
        float* BT = sBeta + sidx * SUBN * 8;
        float* RT = sRT + sidx * SUBINT * 8;
        const float* LB = sidx ? LB1 : LB0;
        UPNODE(BT, RT, LB, 0);
    }
    __syncthreads();

    // ---- publish subtree roots, spin-sync within bg ----
    if (tid < 16) {
        const int sidx = tid >> 3;
        const int q = 2 * q8 + sidx;
        g_rootB[bg][q * 8 + i] = sBeta[sidx * SUBN * 8 + i];
        g_rootW[bg][q * 8 + i] = sRT[sidx * SUBINT * 8 + i];
    }
    __threadfence();
    __syncthreads();
    if (tid == 0) {
        atomicAdd(&g_cnt[bg], 1u);
        while (((volatile unsigned*)g_cnt)[bg] < 8u) __nanosleep(64);
    }
    __syncthreads();
    __threadfence();

    if (tid < 128) {
        const int p = tid >> 3;
        sRootB[tid] = ((volatile float*)g_rootB[bg])[p * 8 + i];
        sRootW[tid] = ((volatile float*)g_rootW[bg])[p * 8 + i];
    }
    __syncthreads();

    float accB = 0.f, accPi = 0.f;

    // ======== top-tree (nodes 0..20), recomputed redundantly ========
    if (tid < 32) {
        const int g4 = grp;
        float tb = 0.f;
        const float4* cp = (const float4*)&sRootB[(4 * g4) * 8];
        #pragma unroll
        for (int j = 0; j < 4; j++) {
            float4 x = cp[2 * j], y = cp[2 * j + 1];
            tb = fmaf(sA_SP[(0 * 4 + j) * 8 + i], x.x, tb);
            tb = fmaf(sA_SP[(1 * 4 + j) * 8 + i], x.y, tb);
            tb = fmaf(sA_SP[(2 * 4 + j) * 8 + i], x.z, tb);
            tb = fmaf(sA_SP[(3 * 4 + j) * 8 + i], x.w, tb);
            tb = fmaf(sA_SP[(4 * 4 + j) * 8 + i], y.x, tb);
            tb = fmaf(sA_SP[(5 * 4 + j) * 8 + i], y.y, tb);
            tb = fmaf(sA_SP[(6 * 4 + j) * 8 + i], y.z, tb);
            tb = fmaf(sA_SP[(7 * 4 + j) * 8 + i], y.w, tb);
        }
        const int lbl = __ldg(&lab[1 + g4]);
        const float eL = __expf(__ldg(&Brow[(size_t)lbl * NG]) - lz);
        float s = tb * eL;
        s += __shfl_xor_sync(gmask, s, 1);
        s += __shfl_xor_sync(gmask, s, 2);
        s += __shfl_xor_sync(gmask, s, 4);
        const float w = __fdividef(eL, s);
        sW1[g4 * 8 + i] = w;
        sB1[g4 * 8 + i] = tb * w;
    }
    __syncthreads();

    if (tid < 8) {
        float tb = 0.f;
        #pragma unroll
        for (int j = 0; j < 4; j++)
            #pragma unroll
            for (int k = 0; k < 8; k++)
                tb = fmaf(sA_SP[(k * 4 + j) * 8 + i], sB1[j * 8 + k], tb);
        const int lbl = __ldg(&lab[0]);
        const float lB = __ldg(&Brow[(size_t)lbl * NG]) - lz;
        const float eL = __expf(lB);
        float s = tb * eL;
        s += __shfl_xor_sync(gmask, s, 1);
        s += __shfl_xor_sync(gmask, s, 2);
        s += __shfl_xor_sync(gmask, s, 4);
        const float w = __fdividef(eL, s);
        sRr[i] = w;
        if (top) accB = fmaf(tb * w, lB, accB);
    }
    __syncthreads();

    if (tid < 32) {
        const int j = grp;
        float dot = 0.f;
        #pragma unroll
        for (int ii = 0; ii < 8; ii++)
            dot = fmaf(sRr[ii], sAT[ii * 32 + i * 4 + j], dot);
        const float ev = sB1[j * 8 + i] * dot;
        sR1[j * 8 + i] = dot * sW1[j * 8 + i];
        if (top) {
            const int lbl = __ldg(&lab[1 + j]);
            accB = fmaf(ev, __ldg(&Brow[(size_t)lbl * NG]) - lz, accB);
            const float rr = sRr[i];
            #pragma unroll
            for (int k = 0; k < 8; k++)
                atomicAdd(&sT[(k * 4 + j) * 8 + i],
                          rr * sA_SP[(k * 4 + j) * 8 + i] * sB1[j * 8 + k]);
        }
    }
    __syncthreads();

    if (tid < 128) {
        const int p = tid >> 3;
        const int nidx = p >> 2;
        const int j = p & 3;
        float dot = 0.f;
        #pragma unroll
        for (int ii = 0; ii < 8; ii++)
            dot = fmaf(sR1[nidx * 8 + ii], sAT[ii * 32 + i * 4 + j], dot);
        const float ev = sRootB[p * 8 + i] * dot;
        const float r2 = dot * sRootW[p * 8 + i];
        if (p == 2 * q8)     sRT[i] = r2;
        if (p == 2 * q8 + 1) sRT[SUBINT * 8 + i] = r2;
        if (top) {
            const int lbl = __ldg(&lab[5 + p]);
            accB = fmaf(ev, __ldg(&Brow[(size_t)lbl * NG]) - lz, accB);
            const float r1v = sR1[nidx * 8 + i];
            #pragma unroll
            for (int k = 0; k < 8; k++)
                atomicAdd(&sT[(k * 4 + j) * 8 + i],
                          r1v * sA_SP[(k * 4 + j) * 8 + i] * sRootB[p * 8 + k]);
        }
    }
    __syncthreads();

    // ======== DOWN ========
    if (grp < 2) {
        const int sidx = grp;
        float* BT = sBeta + sidx * SUBN * 8;
        float* RT = sRT + sidx * SUBINT * 8;
        const float* LB = sidx ? LB1 : LB0;
        DOWNNODE(BT, RT, LB, 0, false);
    }
    __syncthreads();

    if (grp < 8) {
        const int sidx = grp >> 2;
        const int jn = grp & 3;
        float* BT = sBeta + sidx * SUBN * 8;
        float* RT = sRT + sidx * SUBINT * 8;
        const float* LB = sidx ? LB1 : LB0;
        DOWNNODE(BT, RT, LB, 1 + jn, false);
    }
    __syncthreads();

    {
        const int sidx = grp >> 4;
        const int c = grp & 15;
        float* BT = sBeta + sidx * SUBN * 8;
        float* RT = sRT + sidx * SUBINT * 8;
        const float* LB = sidx ? LB1 : LB0;
        DOWNNODE(BT, RT, LB, 5 + c, false);
        __syncwarp();
        #pragma unroll
        for (int t = 0; t < 4; t++)
            DOWNNODE(BT, RT, LB, 21 + 4 * c + t, true);
    }
    __syncthreads();

    // ======== vectorized T post-pass (private slice banks) ========
    {
        const int slice = tid >> 6;
        const int jp = (tid >> 4) & 3;
        const int kh = (tid >> 3) & 1;
        const int ip = tid & 7;
        float a0 = 0.f, a1 = 0.f, a2 = 0.f, a3 = 0.f;
        #pragma unroll
        for (int sidx = 0; sidx < 2; sidx++) {
            const float* RTp = sRT + sidx * SUBINT * 8 + slice * 8 + ip;
            const float* BTp = sBeta + sidx * SUBN * 8 + (4 * slice + 1 + jp) * 8 + kh * 4;
            #pragma unroll 4
            for (int m = slice; m < SUBINT; m += 4) {
                const float r = *RTp;
                const float4 bv = *(const float4*)BTp;
                a0 = fmaf(r, bv.x, a0);
                a1 = fmaf(r, bv.y, a1);
                a2 = fmaf(r, bv.z, a2);
                a3 = fmaf(r, bv.w, a3);
                RTp += 32;
                BTp += 128;
            }
        }
        const int k0 = kh * 4;
        float* bank = sTp + slice * 256;
        bank[((k0 + 0) * 4 + jp) * 8 + ip] = a0 * sA_SP[((k0 + 0) * 4 + jp) * 8 + ip];
        bank[((k0 + 1) * 4 + jp) * 8 + ip] = a1 * sA_SP[((k0 + 1) * 4 + jp) * 8 + ip];
        bank[((k0 + 2) * 4 + jp) * 8 + ip] = a2 * sA_SP[((k0 + 2) * 4 + jp) * 8 + ip];
        bank[((k0 + 3) * 4 + jp) * 8 + ip] = a3 * sA_SP[((k0 + 3) * 4 + jp) * 8 + ip];
    }
    __syncthreads();
    {
        const float tsum = (sTp[tid] + sTp[256 + tid]) + (sTp[512 + tid] + sTp[768 + tid]);
        sT[tid] += tsum;
    }

    // ---- scalar reductions ----
    #pragma unroll
    for (int off = 1; off < 32; off <<= 1) {
        accB += __shfl_xor_sync(0xFFFFFFFFu, accB, off);
        accPi += __shfl_xor_sync(0xFFFFFFFFu, accPi, off);
    }
    if ((tid & 31) == 0) {
        atomicAdd(&sBl, accB);
        atomicAdd(&sPil, accPi);
    }
    __syncthreads();

    atomicAdd(&g_T[bg * 256 + tid], sT[tid]);
    if (tid == 0) {
        atomicAdd(&g_scal[bg * 2 + 0], sBl);
        atomicAdd(&g_scal[bg * 2 + 1], sPil);
    }

    // ======== fused epilogue ========
    __threadfence();
    __syncthreads();
    if (tid == 0) sRank = atomicAdd(&g_cnt2[bg], 1u);
    __syncthreads();
    if (sRank == 7u) {
        __threadfence();
        const float T = g_T[bg * 256 + tid];
        const int kj = tid >> 3;
        const int ii = tid & 7;
        const int j = kj & 3;
        const int k = kj >> 2;
        float t[8]; float mxv = -1e30f;
        #pragma unroll
        for (int c = 0; c < 8; c++) {
            t[c] = __ldg(&A[(size_t)(c * 32 + kj) * NG + g]);
            mxv = fmaxf(mxv, t[c]);
        }
        float s = 0.f;
        #pragma unroll
        for (int c = 0; c < 8; c++) s += __expf(t[c] - mxv);
        float logA = 0.f;
        #pragma unroll
        for (int c = 0; c < 8; c++)
            if (c == ii) logA = t[c] - mxv - __logf(s);
        atomicAdd(&sAred[j], T * logA);
        __syncthreads();
        const float ll = sAred[j] + g_scal[bg * 2 + 0] + g_scal[bg * 2 + 1]
                       + T * sLogSP[j];
        out[((((size_t)b * 8 + ii) * 8 + k) * 4 + j) * NG + g] = -ll;
    }
}

#define TREE_DYN_BYTES ((2 * SUBN * 8 + 2 * SUBINT * 8 + 4 * 256) * 4)  // 31360 B

extern "C" void kernel_launch(void* const* d_in, const int* in_sizes, int n_in,
                              void* d_out, int out_size) {
    const int*   labels = (const int*)d_in[0];
    const float* A      = (const float*)d_in[1];
    const float* Bmat   = (const float*)d_in[2];
    const float* Pi     = (const float*)d_in[3];
    const float* SP     = (const float*)d_in[4];
    float* out = (float*)d_out;

    cudaFuncSetAttribute(tree_kernel,
                         cudaFuncAttributeMaxDynamicSharedMemorySize, TREE_DYN_BYTES);

    zsum_kernel<<<256, 256>>>(Bmat);
    prep_kernel<<<1024, 256>>>(labels, Bmat, Pi);
    tree_kernel<<<TBLKS, 256, TREE_DYN_BYTES>>>(labels, A, Bmat, Pi, SP, out);
}